// round 15
// baseline (speedup 1.0000x reference)
#include <cuda_runtime.h>
#include <cuda_bf16.h>
#include <math.h>

#define B_   4
#define SEQ  2048
#define DM   256
#define NH   4
#define DH   64
#define BHT  16       // B_*NH

// ---------------- scratch (device globals; no allocation) ----------------
__device__ float g_Q [BHT * SEQ * DH];   // [bh][s][64] tf32-rounded, k-permuted, x1/8
__device__ float g_K [BHT * SEQ * DH];   // effective K = K·G^T, tf32-rounded, k-permuted
__device__ float g_V [BHT * SEQ * DH];   // tf32-rounded, plain layout
__device__ float g_O [B_  * SEQ * DM];   // attn output
__device__ float g_Wk[DM * DM];          // folded Wk_eff
__device__ float g_bk[DM];               // folded bk_eff

// ---------------- helpers ----------------
__device__ __forceinline__ unsigned f2tf(float f) {
    unsigned u; asm("cvt.rna.tf32.f32 %0, %1;" : "=r"(u) : "f"(f)); return u;
}
__device__ __forceinline__ void mma8(float c[4], const unsigned a[4], unsigned b0, unsigned b1) {
    asm volatile(
        "mma.sync.aligned.m16n8k8.row.col.f32.tf32.tf32.f32 "
        "{%0,%1,%2,%3}, {%4,%5,%6,%7}, {%8,%9}, {%0,%1,%2,%3};\n"
        : "+f"(c[0]), "+f"(c[1]), "+f"(c[2]), "+f"(c[3])
        : "r"(a[0]), "r"(a[1]), "r"(a[2]), "r"(a[3]), "r"(b0), "r"(b1));
}
__device__ __forceinline__ void mmabf(float c[4], const unsigned a[4], unsigned b0, unsigned b1) {
    asm volatile(
        "mma.sync.aligned.m16n8k16.row.col.f32.bf16.bf16.f32 "
        "{%0,%1,%2,%3}, {%4,%5,%6,%7}, {%8,%9}, {%0,%1,%2,%3};\n"
        : "+f"(c[0]), "+f"(c[1]), "+f"(c[2]), "+f"(c[3])
        : "r"(a[0]), "r"(a[1]), "r"(a[2]), "r"(a[3]), "r"(b0), "r"(b1));
}
__device__ __forceinline__ void bsplit(float x, unsigned short& hi, unsigned short& lo) {
    __nv_bfloat16 h = __float2bfloat16_rn(x);
    float r = x - __bfloat162float(h);
    __nv_bfloat16 l = __float2bfloat16_rn(r);
    hi = *(unsigned short*)&h;
    lo = *(unsigned short*)&l;
}
// permute within 8-group so (k, k+4) land adjacent: j<4 -> 2j ; j>=4 -> 2j-7
__device__ __forceinline__ int p8(int j) { return (j < 4) ? 2 * j : 2 * j - 7; }

// =====================================================================
// Kernel 0: prep — fold TT interaction into Wk.
//   M_h[d,e] = sum_{a,r} W2[h,d,a,r] * W2[h,a,e,r];  G = I + (alpha/64) M
// =====================================================================
#define PREP_SMEM ((64 * 256 + 64 * 65) * 4)

__global__ __launch_bounds__(256) void prep_kernel(const float* __restrict__ W2,
                                                   const float* __restrict__ alpha_p,
                                                   const float* __restrict__ Wk,
                                                   const float* __restrict__ bk)
{
    extern __shared__ float sm[];
    float* Ws = sm;              // 64 x 256
    float* Gs = sm + 64 * 256;   // 64 x 65
    const int h = blockIdx.x;
    const int tid = threadIdx.x;
    const float* W2h = W2 + (size_t)h * 64 * 256;

    for (int idx = tid; idx < 64 * 256; idx += 256) Ws[idx] = W2h[idx];
    __syncthreads();

    const float c = alpha_p[0] * (1.0f / 64.0f);
    for (int idx = tid; idx < 64 * 64; idx += 256) {
        int d = idx >> 6, e = idx & 63;
        float s = 0.f;
        #pragma unroll 8
        for (int a = 0; a < 64; a++) {
            float4 wa = *(const float4*)&Ws[d * 256 + a * 4];
            float4 wb = *(const float4*)&Ws[a * 256 + e * 4];
            s += wa.x * wb.x + wa.y * wb.y + wa.z * wb.z + wa.w * wb.w;
        }
        Gs[d * 65 + e] = c * s + ((d == e) ? 1.0f : 0.0f);
    }
    __syncthreads();

    {
        const int cr = tid;
        float kin[64];
        #pragma unroll
        for (int e = 0; e < 64; e++) kin[e] = Wk[(size_t)cr * DM + h * 64 + e];
        for (int d = 0; d < 64; d++) {
            float s = 0.f;
            #pragma unroll
            for (int e = 0; e < 64; e++) s += kin[e] * Gs[d * 65 + e];
            g_Wk[(size_t)cr * DM + h * 64 + d] = s;
        }
    }
    if (tid < 64) {
        int d = tid;
        float s = 0.f;
        #pragma unroll
        for (int e = 0; e < 64; e++) s += bk[h * 64 + e] * Gs[d * 65 + e];
        g_bk[h * 64 + d] = s;
    }
}

// =====================================================================
// Kernel 1: QKV projection — bf16-split mma (Ah·Bh + Al·Bh + Ah·Bl).
// 64x64 tile, 8 warps: warp w -> m-strip (w&3)*16, n-half (w>>2)*32 (4 n-tiles).
// Epilogue: Q/K -> tf32-rounded, k-permuted scatter; V -> tf32-rounded plain.
// =====================================================================
__global__ __launch_bounds__(256) void proj_kernel(
    const float* __restrict__ Xq, const float* __restrict__ Xk, const float* __restrict__ Xv,
    const float* __restrict__ Wq, const float* __restrict__ bq,
    const float* __restrict__ Wv, const float* __restrict__ bv)
{
    __shared__ unsigned short Ah[64 * 18], Al[64 * 18];
    __shared__ unsigned short Bh[64 * 18], Bl[64 * 18];
    const int z = blockIdx.z;
    const float* X    = (z == 0) ? Xq : (z == 1) ? Xk : Xv;
    const float* W    = (z == 0) ? Wq : (z == 1) ? g_Wk : Wv;
    const float* bias = (z == 0) ? bq : (z == 1) ? g_bk : bv;
    const int m0 = blockIdx.x * 64;
    const int n0 = blockIdx.y * 64;
    const int tid  = threadIdx.x;
    const int w    = tid >> 5;
    const int lane = tid & 31;
    const int gid  = lane >> 2, tig = lane & 3;
    const int mrow = (w & 3) * 16;
    const int nc0  = (w >> 2) * 32;

    float acc[4][4] = {};
    for (int k0 = 0; k0 < DM; k0 += 16) {
        {
            int i = tid >> 2, c = tid & 3;
            float4 a = *(const float4*)&X[(size_t)(m0 + i) * DM + k0 + c * 4];
            float av[4] = {a.x, a.y, a.z, a.w};
            #pragma unroll
            for (int u = 0; u < 4; u++)
                bsplit(av[u], Ah[i * 18 + c * 4 + u], Al[i * 18 + c * 4 + u]);
            int kk = tid >> 4, c2 = tid & 15;
            float4 wv = *(const float4*)&W[(size_t)(k0 + kk) * DM + n0 + c2 * 4];
            float wf[4] = {wv.x, wv.y, wv.z, wv.w};
            #pragma unroll
            for (int u = 0; u < 4; u++)
                bsplit(wf[u], Bh[(c2 * 4 + u) * 18 + kk], Bl[(c2 * 4 + u) * 18 + kk]);
        }
        __syncthreads();
        unsigned ah[4], al[4];
        ah[0] = *(const unsigned*)&Ah[(mrow + gid)     * 18 + 2 * tig];
        ah[1] = *(const unsigned*)&Ah[(mrow + gid + 8) * 18 + 2 * tig];
        ah[2] = *(const unsigned*)&Ah[(mrow + gid)     * 18 + 8 + 2 * tig];
        ah[3] = *(const unsigned*)&Ah[(mrow + gid + 8) * 18 + 8 + 2 * tig];
        al[0] = *(const unsigned*)&Al[(mrow + gid)     * 18 + 2 * tig];
        al[1] = *(const unsigned*)&Al[(mrow + gid + 8) * 18 + 2 * tig];
        al[2] = *(const unsigned*)&Al[(mrow + gid)     * 18 + 8 + 2 * tig];
        al[3] = *(const unsigned*)&Al[(mrow + gid + 8) * 18 + 8 + 2 * tig];
        #pragma unroll
        for (int nt = 0; nt < 4; nt++) {
            int n = nc0 + nt * 8 + gid;
            unsigned bh0 = *(const unsigned*)&Bh[n * 18 + 2 * tig];
            unsigned bh1 = *(const unsigned*)&Bh[n * 18 + 8 + 2 * tig];
            unsigned bl0 = *(const unsigned*)&Bl[n * 18 + 2 * tig];
            unsigned bl1 = *(const unsigned*)&Bl[n * 18 + 8 + 2 * tig];
            mmabf(acc[nt], ah, bh0, bh1);
            mmabf(acc[nt], al, bh0, bh1);
            mmabf(acc[nt], ah, bl0, bl1);
        }
        __syncthreads();
    }

    const int h = n0 >> 6;
    float* dst = (z == 0) ? g_Q : (z == 1) ? g_K : g_V;
    const float sc = (z == 0) ? 0.125f : 1.0f;
    const int r0 = m0 + mrow + gid;
    #pragma unroll
    for (int nt = 0; nt < 4; nt++) {
        int ch0 = nc0 + nt * 8 + 2 * tig;     // head-local col
        int ch1 = ch0 + 1;
        float v[2][2];
        v[0][0] = (acc[nt][0] + bias[n0 + ch0]) * sc;
        v[0][1] = (acc[nt][1] + bias[n0 + ch1]) * sc;
        v[1][0] = (acc[nt][2] + bias[n0 + ch0]) * sc;
        v[1][1] = (acc[nt][3] + bias[n0 + ch1]) * sc;
        #pragma unroll
        for (int rr = 0; rr < 2; rr++) {
            int m = r0 + rr * 8;
            int b = m >> 11, s = m & (SEQ - 1);
            size_t base = (size_t)((b * NH + h) * SEQ + s) * DH;
            float t0 = __uint_as_float(f2tf(v[rr][0]));
            float t1 = __uint_as_float(f2tf(v[rr][1]));
            if (z < 2) {   // permuted k layout for Q/K
                dst[base + (ch0 & ~7) + p8(ch0 & 7)] = t0;
                dst[base + (ch1 & ~7) + p8(ch1 & 7)] = t1;
            } else {
                dst[base + ch0] = t0;
                dst[base + ch1] = t1;
            }
        }
    }
}

// =====================================================================
// Kernel 2: flash attention via mma.sync m16n8k8 tf32.
// g_Q/g_K pre-rounded + k-permuted -> S-phase fragments are LDS.64.
// Qs/Ks stride 72 (8B pair-bank = 4*gid+tig, conflict-free); Vs 72; Ps 68.
// =====================================================================
#define ATTN_SMEM ((128 * 72 + 64 * 72 + 64 * 72) * 4)   // 73,728 B

__global__ __launch_bounds__(256, 2) void attn_kernel()
{
    extern __shared__ float sm[];
    float* Qs = sm;                   // 128x72; becomes Ps after prologue
    float* Ps = sm;                   // 128x68 view (tf32 bits of P)
    float* Ks = sm + 128 * 72;        // 64x72
    float* Vs = Ks + 64 * 72;         // 64x72
    const int bh = blockIdx.y;
    const int qt = blockIdx.x;
    const int tid  = threadIdx.x;
    const int w    = tid >> 5;
    const int lane = tid & 31;
    const int gid  = lane >> 2;       // 0..7
    const int tig  = lane & 3;        // 0..3

    // ---- prologue: copy Q tile (pre-rounded, permuted) ----
    const float* Qg = g_Q + (size_t)(bh * SEQ + qt * 128) * DH;
    #pragma unroll
    for (int it = 0; it < 8; it++) {
        int idx = tid + it * 256;
        int i = idx >> 4, c = idx & 15;
        *(float4*)&Qs[i * 72 + c * 4] = *(const float4*)&Qg[i * DH + c * 4];
    }
    __syncthreads();

    // ---- Q fragments to registers (LDS.64 pairs) ----
    const int qrow = w * 16 + gid;
    unsigned aq[8][4];
    #pragma unroll
    for (int k0 = 0; k0 < 8; k0++) {
        uint2 qa = *(const uint2*)&Qs[qrow * 72 + k0 * 8 + 2 * tig];
        uint2 qb = *(const uint2*)&Qs[(qrow + 8) * 72 + k0 * 8 + 2 * tig];
        aq[k0][0] = qa.x; aq[k0][1] = qb.x; aq[k0][2] = qa.y; aq[k0][3] = qb.y;
    }

    float m0 = -1e30f, m1 = -1e30f, l0 = 0.f, l1 = 0.f;
    float o[8][4] = {};

    for (int kt = 0; kt < 32; kt++) {
        const float* Kg = g_K + (size_t)(bh * SEQ + kt * 64) * DH;
        const float* Vg = g_V + (size_t)(bh * SEQ + kt * 64) * DH;
        #pragma unroll
        for (int it = 0; it < 4; it++) {
            int idx = tid + it * 256;
            int i = idx >> 4, c = idx & 15;
            *(float4*)&Ks[i * 72 + c * 4] = *(const float4*)&Kg[i * DH + c * 4];
            *(float4*)&Vs[i * 72 + c * 4] = *(const float4*)&Vg[i * DH + c * 4];
        }
        __syncthreads();

        // ---- S[16x64] = Q . K^T  (b fragment = one LDS.64) ----
        float s[8][4] = {};
        #pragma unroll
        for (int k0 = 0; k0 < 8; k0++) {
            #pragma unroll
            for (int n0 = 0; n0 < 8; n0++) {
                uint2 bb = *(const uint2*)&Ks[(n0 * 8 + gid) * 72 + k0 * 8 + 2 * tig];
                mma8(s[n0], aq[k0], bb.x, bb.y);
            }
        }

        // ---- online softmax (rows qrow and qrow+8) ----
        float rx0 = -1e30f, rx1 = -1e30f;
        #pragma unroll
        for (int n0 = 0; n0 < 8; n0++) {
            rx0 = fmaxf(rx0, fmaxf(s[n0][0], s[n0][1]));
            rx1 = fmaxf(rx1, fmaxf(s[n0][2], s[n0][3]));
        }
        rx0 = fmaxf(rx0, __shfl_xor_sync(0xffffffffu, rx0, 1));
        rx0 = fmaxf(rx0, __shfl_xor_sync(0xffffffffu, rx0, 2));
        rx1 = fmaxf(rx1, __shfl_xor_sync(0xffffffffu, rx1, 1));
        rx1 = fmaxf(rx1, __shfl_xor_sync(0xffffffffu, rx1, 2));
        float mn0 = fmaxf(m0, rx0), mn1 = fmaxf(m1, rx1);
        float corr0 = __expf(m0 - mn0), corr1 = __expf(m1 - mn1);
        m0 = mn0; m1 = mn1;
        float rs0 = 0.f, rs1 = 0.f;
        #pragma unroll
        for (int n0 = 0; n0 < 8; n0++) {
            float p0 = __expf(s[n0][0] - mn0);
            float p1 = __expf(s[n0][1] - mn0);
            float p2 = __expf(s[n0][2] - mn1);
            float p3 = __expf(s[n0][3] - mn1);
            rs0 += p0 + p1; rs1 += p2 + p3;
            o[n0][0] *= corr0; o[n0][1] *= corr0;
            o[n0][2] *= corr1; o[n0][3] *= corr1;
            *(float2*)&Ps[qrow * 68 + n0 * 8 + 2 * tig] =
                make_float2(__uint_as_float(f2tf(p0)), __uint_as_float(f2tf(p1)));
            *(float2*)&Ps[(qrow + 8) * 68 + n0 * 8 + 2 * tig] =
                make_float2(__uint_as_float(f2tf(p2)), __uint_as_float(f2tf(p3)));
        }
        rs0 += __shfl_xor_sync(0xffffffffu, rs0, 1);
        rs0 += __shfl_xor_sync(0xffffffffu, rs0, 2);
        rs1 += __shfl_xor_sync(0xffffffffu, rs1, 1);
        rs1 += __shfl_xor_sync(0xffffffffu, rs1, 2);
        l0 = l0 * corr0 + rs0;
        l1 = l1 * corr1 + rs1;
        __syncwarp();

        // ---- O[16x64] += P . V ----
        #pragma unroll
        for (int k0 = 0; k0 < 8; k0++) {
            unsigned ap[4];
            ap[0] = __float_as_uint(Ps[qrow * 68 + k0 * 8 + tig]);
            ap[1] = __float_as_uint(Ps[(qrow + 8) * 68 + k0 * 8 + tig]);
            ap[2] = __float_as_uint(Ps[qrow * 68 + k0 * 8 + tig + 4]);
            ap[3] = __float_as_uint(Ps[(qrow + 8) * 68 + k0 * 8 + tig + 4]);
            #pragma unroll
            for (int n0 = 0; n0 < 8; n0++) {
                unsigned b0 = __float_as_uint(Vs[(k0 * 8 + tig) * 72 + n0 * 8 + gid]);
                unsigned b1 = __float_as_uint(Vs[(k0 * 8 + tig + 4) * 72 + n0 * 8 + gid]);
                mma8(o[n0], ap, b0, b1);
            }
        }
        __syncthreads();
    }

    // ---- epilogue: normalize, write g_O ----
    const float inv0 = 1.0f / l0, inv1 = 1.0f / l1;
    const int bb = bh >> 2, h = bh & 3;
    const int r0 = qt * 128 + qrow;
    size_t base0 = (size_t)(bb * SEQ + r0) * DM + h * 64;
    size_t base1 = base0 + (size_t)8 * DM;
    #pragma unroll
    for (int n0 = 0; n0 < 8; n0++) {
        *(float2*)&g_O[base0 + n0 * 8 + 2 * tig] =
            make_float2(o[n0][0] * inv0, o[n0][1] * inv0);
        *(float2*)&g_O[base1 + n0 * 8 + 2 * tig] =
            make_float2(o[n0][2] * inv1, o[n0][3] * inv1);
    }
}

// =====================================================================
// Kernel 3: output projection — bf16-split mma.  d_out = g_O @ Wo + bo
// =====================================================================
__global__ __launch_bounds__(256) void out_kernel(const float* __restrict__ Wo,
                                                  const float* __restrict__ bo,
                                                  float* __restrict__ out)
{
    __shared__ unsigned short Ah[64 * 18], Al[64 * 18];
    __shared__ unsigned short Bh[64 * 18], Bl[64 * 18];
    const int m0 = blockIdx.x * 64;
    const int n0 = blockIdx.y * 64;
    const int tid  = threadIdx.x;
    const int w    = tid >> 5;
    const int lane = tid & 31;
    const int gid  = lane >> 2, tig = lane & 3;
    const int mrow = (w & 3) * 16;
    const int nc0  = (w >> 2) * 32;

    float acc[4][4] = {};
    for (int k0 = 0; k0 < DM; k0 += 16) {
        {
            int i = tid >> 2, c = tid & 3;
            float4 a = *(const float4*)&g_O[(size_t)(m0 + i) * DM + k0 + c * 4];
            float av[4] = {a.x, a.y, a.z, a.w};
            #pragma unroll
            for (int u = 0; u < 4; u++)
                bsplit(av[u], Ah[i * 18 + c * 4 + u], Al[i * 18 + c * 4 + u]);
            int kk = tid >> 4, c2 = tid & 15;
            float4 wv = *(const float4*)&Wo[(size_t)(k0 + kk) * DM + n0 + c2 * 4];
            float wf[4] = {wv.x, wv.y, wv.z, wv.w};
            #pragma unroll
            for (int u = 0; u < 4; u++)
                bsplit(wf[u], Bh[(c2 * 4 + u) * 18 + kk], Bl[(c2 * 4 + u) * 18 + kk]);
        }
        __syncthreads();
        unsigned ah[4], al[4];
        ah[0] = *(const unsigned*)&Ah[(mrow + gid)     * 18 + 2 * tig];
        ah[1] = *(const unsigned*)&Ah[(mrow + gid + 8) * 18 + 2 * tig];
        ah[2] = *(const unsigned*)&Ah[(mrow + gid)     * 18 + 8 + 2 * tig];
        ah[3] = *(const unsigned*)&Ah[(mrow + gid + 8) * 18 + 8 + 2 * tig];
        al[0] = *(const unsigned*)&Al[(mrow + gid)     * 18 + 2 * tig];
        al[1] = *(const unsigned*)&Al[(mrow + gid + 8) * 18 + 2 * tig];
        al[2] = *(const unsigned*)&Al[(mrow + gid)     * 18 + 8 + 2 * tig];
        al[3] = *(const unsigned*)&Al[(mrow + gid + 8) * 18 + 8 + 2 * tig];
        #pragma unroll
        for (int nt = 0; nt < 4; nt++) {
            int n = nc0 + nt * 8 + gid;
            unsigned bh0 = *(const unsigned*)&Bh[n * 18 + 2 * tig];
            unsigned bh1 = *(const unsigned*)&Bh[n * 18 + 8 + 2 * tig];
            unsigned bl0 = *(const unsigned*)&Bl[n * 18 + 2 * tig];
            unsigned bl1 = *(const unsigned*)&Bl[n * 18 + 8 + 2 * tig];
            mmabf(acc[nt], ah, bh0, bh1);
            mmabf(acc[nt], al, bh0, bh1);
            mmabf(acc[nt], ah, bl0, bl1);
        }
        __syncthreads();
    }

    const int r0 = m0 + mrow + gid;
    #pragma unroll
    for (int nt = 0; nt < 4; nt++) {
        int c0 = n0 + nc0 + nt * 8 + 2 * tig;
        *(float2*)&out[(size_t)r0 * DM + c0] =
            make_float2(acc[nt][0] + bo[c0], acc[nt][1] + bo[c0 + 1]);
        *(float2*)&out[(size_t)(r0 + 8) * DM + c0] =
            make_float2(acc[nt][2] + bo[c0], acc[nt][3] + bo[c0 + 1]);
    }
}

// =====================================================================
extern "C" void kernel_launch(void* const* d_in, const int* in_sizes, int n_in,
                              void* d_out, int out_size)
{
    const float* query = (const float*)d_in[0];
    const float* key_  = (const float*)d_in[1];
    const float* value = (const float*)d_in[2];
    const float* Wq    = (const float*)d_in[3];
    const float* bq    = (const float*)d_in[4];
    const float* Wk    = (const float*)d_in[5];
    const float* bk    = (const float*)d_in[6];
    const float* Wv    = (const float*)d_in[7];
    const float* bv    = (const float*)d_in[8];
    const float* W2    = (const float*)d_in[9];
    const float* alpha = (const float*)d_in[10];
    const float* Wo    = (const float*)d_in[11];
    const float* bo    = (const float*)d_in[12];
    float* out = (float*)d_out;

    cudaFuncSetAttribute(prep_kernel, cudaFuncAttributeMaxDynamicSharedMemorySize, PREP_SMEM);
    cudaFuncSetAttribute(attn_kernel, cudaFuncAttributeMaxDynamicSharedMemorySize, ATTN_SMEM);

    prep_kernel<<<NH, 256, PREP_SMEM>>>(W2, alpha, Wk, bk);
    proj_kernel<<<dim3(128, 4, 3), 256>>>(query, key_, value, Wq, bq, Wv, bv);
    attn_kernel<<<dim3(16, BHT), 256, ATTN_SMEM>>>();
    out_kernel<<<dim3(128, 4), 256>>>(Wo, bo, out);
}

// round 16
// speedup vs baseline: 1.0047x; 1.0047x over previous
#include <cuda_runtime.h>
#include <cuda_bf16.h>
#include <math.h>

#define B_   4
#define SEQ  2048
#define DM   256
#define NH   4
#define DH   64
#define BHT  16       // B_*NH

// ---------------- scratch (device globals; no allocation) ----------------
__device__ float g_Q [BHT * SEQ * DH];   // [bh][s][64] tf32-rounded, k-permuted, x1/8
__device__ float g_K [BHT * SEQ * DH];   // effective K = K·G^T, tf32-rounded, k-permuted
__device__ float g_V [BHT * SEQ * DH];   // tf32-rounded, plain layout
__device__ float g_O [B_  * SEQ * DM];   // attn output
__device__ float g_Wk[DM * DM];          // folded Wk_eff
__device__ float g_bk[DM];               // folded bk_eff

// ---------------- helpers ----------------
__device__ __forceinline__ unsigned f2tf(float f) {
    unsigned u; asm("cvt.rna.tf32.f32 %0, %1;" : "=r"(u) : "f"(f)); return u;
}
__device__ __forceinline__ void mma8(float c[4], const unsigned a[4], unsigned b0, unsigned b1) {
    asm volatile(
        "mma.sync.aligned.m16n8k8.row.col.f32.tf32.tf32.f32 "
        "{%0,%1,%2,%3}, {%4,%5,%6,%7}, {%8,%9}, {%0,%1,%2,%3};\n"
        : "+f"(c[0]), "+f"(c[1]), "+f"(c[2]), "+f"(c[3])
        : "r"(a[0]), "r"(a[1]), "r"(a[2]), "r"(a[3]), "r"(b0), "r"(b1));
}
__device__ __forceinline__ void mmabf(float c[4], const unsigned a[4], unsigned b0, unsigned b1) {
    asm volatile(
        "mma.sync.aligned.m16n8k16.row.col.f32.bf16.bf16.f32 "
        "{%0,%1,%2,%3}, {%4,%5,%6,%7}, {%8,%9}, {%0,%1,%2,%3};\n"
        : "+f"(c[0]), "+f"(c[1]), "+f"(c[2]), "+f"(c[3])
        : "r"(a[0]), "r"(a[1]), "r"(a[2]), "r"(a[3]), "r"(b0), "r"(b1));
}
__device__ __forceinline__ void bsplit(float x, unsigned short& hi, unsigned short& lo) {
    __nv_bfloat16 h = __float2bfloat16_rn(x);
    float r = x - __bfloat162float(h);
    __nv_bfloat16 l = __float2bfloat16_rn(r);
    hi = *(unsigned short*)&h;
    lo = *(unsigned short*)&l;
}
// permute within 8-group so (k, k+4) land adjacent: j<4 -> 2j ; j>=4 -> 2j-7
__device__ __forceinline__ int p8(int j) { return (j < 4) ? 2 * j : 2 * j - 7; }

// =====================================================================
// Kernel 0: prep — fold TT interaction into Wk.
//   M_h[d,e] = sum_{a,r} W2[h,d,a,r] * W2[h,a,e,r];  G = I + (alpha/64) M
// =====================================================================
#define PREP_SMEM ((64 * 256 + 64 * 65) * 4)

__global__ __launch_bounds__(256) void prep_kernel(const float* __restrict__ W2,
                                                   const float* __restrict__ alpha_p,
                                                   const float* __restrict__ Wk,
                                                   const float* __restrict__ bk)
{
    extern __shared__ float sm[];
    float* Ws = sm;              // 64 x 256
    float* Gs = sm + 64 * 256;   // 64 x 65
    const int h = blockIdx.x;
    const int tid = threadIdx.x;
    const float* W2h = W2 + (size_t)h * 64 * 256;

    for (int idx = tid; idx < 64 * 256; idx += 256) Ws[idx] = W2h[idx];
    __syncthreads();

    const float c = alpha_p[0] * (1.0f / 64.0f);
    for (int idx = tid; idx < 64 * 64; idx += 256) {
        int d = idx >> 6, e = idx & 63;
        float s = 0.f;
        #pragma unroll 8
        for (int a = 0; a < 64; a++) {
            float4 wa = *(const float4*)&Ws[d * 256 + a * 4];
            float4 wb = *(const float4*)&Ws[a * 256 + e * 4];
            s += wa.x * wb.x + wa.y * wb.y + wa.z * wb.z + wa.w * wb.w;
        }
        Gs[d * 65 + e] = c * s + ((d == e) ? 1.0f : 0.0f);
    }
    __syncthreads();

    {
        const int cr = tid;
        float kin[64];
        #pragma unroll
        for (int e = 0; e < 64; e++) kin[e] = Wk[(size_t)cr * DM + h * 64 + e];
        for (int d = 0; d < 64; d++) {
            float s = 0.f;
            #pragma unroll
            for (int e = 0; e < 64; e++) s += kin[e] * Gs[d * 65 + e];
            g_Wk[(size_t)cr * DM + h * 64 + d] = s;
        }
    }
    if (tid < 64) {
        int d = tid;
        float s = 0.f;
        #pragma unroll
        for (int e = 0; e < 64; e++) s += bk[h * 64 + e] * Gs[d * 65 + e];
        g_bk[h * 64 + d] = s;
    }
}

// =====================================================================
// Kernel 1: QKV projection — bf16-split mma (Ah·Bh + Al·Bh + Ah·Bl).
// 64x64 tile, 8 warps: warp w -> m-strip (w&3)*16, n-half (w>>2)*32 (4 n-tiles).
// Epilogue: Q/K -> tf32-rounded, k-permuted scatter; V -> tf32-rounded plain.
// =====================================================================
__global__ __launch_bounds__(256) void proj_kernel(
    const float* __restrict__ Xq, const float* __restrict__ Xk, const float* __restrict__ Xv,
    const float* __restrict__ Wq, const float* __restrict__ bq,
    const float* __restrict__ Wv, const float* __restrict__ bv)
{
    __shared__ unsigned short Ah[64 * 18], Al[64 * 18];
    __shared__ unsigned short Bh[64 * 18], Bl[64 * 18];
    const int z = blockIdx.z;
    const float* X    = (z == 0) ? Xq : (z == 1) ? Xk : Xv;
    const float* W    = (z == 0) ? Wq : (z == 1) ? g_Wk : Wv;
    const float* bias = (z == 0) ? bq : (z == 1) ? g_bk : bv;
    const int m0 = blockIdx.x * 64;
    const int n0 = blockIdx.y * 64;
    const int tid  = threadIdx.x;
    const int w    = tid >> 5;
    const int lane = tid & 31;
    const int gid  = lane >> 2, tig = lane & 3;
    const int mrow = (w & 3) * 16;
    const int nc0  = (w >> 2) * 32;

    float acc[4][4] = {};
    for (int k0 = 0; k0 < DM; k0 += 16) {
        {
            int i = tid >> 2, c = tid & 3;
            float4 a = *(const float4*)&X[(size_t)(m0 + i) * DM + k0 + c * 4];
            float av[4] = {a.x, a.y, a.z, a.w};
            #pragma unroll
            for (int u = 0; u < 4; u++)
                bsplit(av[u], Ah[i * 18 + c * 4 + u], Al[i * 18 + c * 4 + u]);
            int kk = tid >> 4, c2 = tid & 15;
            float4 wv = *(const float4*)&W[(size_t)(k0 + kk) * DM + n0 + c2 * 4];
            float wf[4] = {wv.x, wv.y, wv.z, wv.w};
            #pragma unroll
            for (int u = 0; u < 4; u++)
                bsplit(wf[u], Bh[(c2 * 4 + u) * 18 + kk], Bl[(c2 * 4 + u) * 18 + kk]);
        }
        __syncthreads();
        unsigned ah[4], al[4];
        ah[0] = *(const unsigned*)&Ah[(mrow + gid)     * 18 + 2 * tig];
        ah[1] = *(const unsigned*)&Ah[(mrow + gid + 8) * 18 + 2 * tig];
        ah[2] = *(const unsigned*)&Ah[(mrow + gid)     * 18 + 8 + 2 * tig];
        ah[3] = *(const unsigned*)&Ah[(mrow + gid + 8) * 18 + 8 + 2 * tig];
        al[0] = *(const unsigned*)&Al[(mrow + gid)     * 18 + 2 * tig];
        al[1] = *(const unsigned*)&Al[(mrow + gid + 8) * 18 + 2 * tig];
        al[2] = *(const unsigned*)&Al[(mrow + gid)     * 18 + 8 + 2 * tig];
        al[3] = *(const unsigned*)&Al[(mrow + gid + 8) * 18 + 8 + 2 * tig];
        #pragma unroll
        for (int nt = 0; nt < 4; nt++) {
            int n = nc0 + nt * 8 + gid;
            unsigned bh0 = *(const unsigned*)&Bh[n * 18 + 2 * tig];
            unsigned bh1 = *(const unsigned*)&Bh[n * 18 + 8 + 2 * tig];
            unsigned bl0 = *(const unsigned*)&Bl[n * 18 + 2 * tig];
            unsigned bl1 = *(const unsigned*)&Bl[n * 18 + 8 + 2 * tig];
            mmabf(acc[nt], ah, bh0, bh1);
            mmabf(acc[nt], al, bh0, bh1);
            mmabf(acc[nt], ah, bl0, bl1);
        }
        __syncthreads();
    }

    const int h = n0 >> 6;
    float* dst = (z == 0) ? g_Q : (z == 1) ? g_K : g_V;
    const float sc = (z == 0) ? 0.125f : 1.0f;
    const int r0 = m0 + mrow + gid;
    #pragma unroll
    for (int nt = 0; nt < 4; nt++) {
        int ch0 = nc0 + nt * 8 + 2 * tig;     // head-local col
        int ch1 = ch0 + 1;
        float v[2][2];
        v[0][0] = (acc[nt][0] + bias[n0 + ch0]) * sc;
        v[0][1] = (acc[nt][1] + bias[n0 + ch1]) * sc;
        v[1][0] = (acc[nt][2] + bias[n0 + ch0]) * sc;
        v[1][1] = (acc[nt][3] + bias[n0 + ch1]) * sc;
        #pragma unroll
        for (int rr = 0; rr < 2; rr++) {
            int m = r0 + rr * 8;
            int b = m >> 11, s = m & (SEQ - 1);
            size_t base = (size_t)((b * NH + h) * SEQ + s) * DH;
            float t0 = __uint_as_float(f2tf(v[rr][0]));
            float t1 = __uint_as_float(f2tf(v[rr][1]));
            if (z < 2) {   // permuted k layout for Q/K
                dst[base + (ch0 & ~7) + p8(ch0 & 7)] = t0;
                dst[base + (ch1 & ~7) + p8(ch1 & 7)] = t1;
            } else {
                dst[base + ch0] = t0;
                dst[base + ch1] = t1;
            }
        }
    }
}

// =====================================================================
// Kernel 2: flash attention via mma.sync m16n8k8 tf32.
// g_Q/g_K pre-rounded + k-permuted -> S-phase fragments are LDS.64.
// Qs/Ks stride 72 (8B pair-bank = 4*gid+tig, conflict-free); Vs 72; Ps 68.
// =====================================================================
#define ATTN_SMEM ((128 * 72 + 64 * 72 + 64 * 72) * 4)   // 73,728 B

__global__ __launch_bounds__(256, 2) void attn_kernel()
{
    extern __shared__ float sm[];
    float* Qs = sm;                   // 128x72; becomes Ps after prologue
    float* Ps = sm;                   // 128x68 view (tf32 bits of P)
    float* Ks = sm + 128 * 72;        // 64x72
    float* Vs = Ks + 64 * 72;         // 64x72
    const int bh = blockIdx.y;
    const int qt = blockIdx.x;
    const int tid  = threadIdx.x;
    const int w    = tid >> 5;
    const int lane = tid & 31;
    const int gid  = lane >> 2;       // 0..7
    const int tig  = lane & 3;        // 0..3

    // ---- prologue: copy Q tile (pre-rounded, permuted) ----
    const float* Qg = g_Q + (size_t)(bh * SEQ + qt * 128) * DH;
    #pragma unroll
    for (int it = 0; it < 8; it++) {
        int idx = tid + it * 256;
        int i = idx >> 4, c = idx & 15;
        *(float4*)&Qs[i * 72 + c * 4] = *(const float4*)&Qg[i * DH + c * 4];
    }
    __syncthreads();

    // ---- Q fragments to registers (LDS.64 pairs) ----
    const int qrow = w * 16 + gid;
    unsigned aq[8][4];
    #pragma unroll
    for (int k0 = 0; k0 < 8; k0++) {
        uint2 qa = *(const uint2*)&Qs[qrow * 72 + k0 * 8 + 2 * tig];
        uint2 qb = *(const uint2*)&Qs[(qrow + 8) * 72 + k0 * 8 + 2 * tig];
        aq[k0][0] = qa.x; aq[k0][1] = qb.x; aq[k0][2] = qa.y; aq[k0][3] = qb.y;
    }

    float m0 = -1e30f, m1 = -1e30f, l0 = 0.f, l1 = 0.f;
    float o[8][4] = {};

    for (int kt = 0; kt < 32; kt++) {
        const float* Kg = g_K + (size_t)(bh * SEQ + kt * 64) * DH;
        const float* Vg = g_V + (size_t)(bh * SEQ + kt * 64) * DH;
        #pragma unroll
        for (int it = 0; it < 4; it++) {
            int idx = tid + it * 256;
            int i = idx >> 4, c = idx & 15;
            *(float4*)&Ks[i * 72 + c * 4] = *(const float4*)&Kg[i * DH + c * 4];
            *(float4*)&Vs[i * 72 + c * 4] = *(const float4*)&Vg[i * DH + c * 4];
        }
        __syncthreads();

        // ---- S[16x64] = Q . K^T  (b fragment = one LDS.64) ----
        float s[8][4] = {};
        #pragma unroll
        for (int k0 = 0; k0 < 8; k0++) {
            #pragma unroll
            for (int n0 = 0; n0 < 8; n0++) {
                uint2 bb = *(const uint2*)&Ks[(n0 * 8 + gid) * 72 + k0 * 8 + 2 * tig];
                mma8(s[n0], aq[k0], bb.x, bb.y);
            }
        }

        // ---- online softmax (rows qrow and qrow+8) ----
        float rx0 = -1e30f, rx1 = -1e30f;
        #pragma unroll
        for (int n0 = 0; n0 < 8; n0++) {
            rx0 = fmaxf(rx0, fmaxf(s[n0][0], s[n0][1]));
            rx1 = fmaxf(rx1, fmaxf(s[n0][2], s[n0][3]));
        }
        rx0 = fmaxf(rx0, __shfl_xor_sync(0xffffffffu, rx0, 1));
        rx0 = fmaxf(rx0, __shfl_xor_sync(0xffffffffu, rx0, 2));
        rx1 = fmaxf(rx1, __shfl_xor_sync(0xffffffffu, rx1, 1));
        rx1 = fmaxf(rx1, __shfl_xor_sync(0xffffffffu, rx1, 2));
        float mn0 = fmaxf(m0, rx0), mn1 = fmaxf(m1, rx1);
        float corr0 = __expf(m0 - mn0), corr1 = __expf(m1 - mn1);
        m0 = mn0; m1 = mn1;
        float rs0 = 0.f, rs1 = 0.f;
        #pragma unroll
        for (int n0 = 0; n0 < 8; n0++) {
            float p0 = __expf(s[n0][0] - mn0);
            float p1 = __expf(s[n0][1] - mn0);
            float p2 = __expf(s[n0][2] - mn1);
            float p3 = __expf(s[n0][3] - mn1);
            rs0 += p0 + p1; rs1 += p2 + p3;
            o[n0][0] *= corr0; o[n0][1] *= corr0;
            o[n0][2] *= corr1; o[n0][3] *= corr1;
            *(float2*)&Ps[qrow * 68 + n0 * 8 + 2 * tig] =
                make_float2(__uint_as_float(f2tf(p0)), __uint_as_float(f2tf(p1)));
            *(float2*)&Ps[(qrow + 8) * 68 + n0 * 8 + 2 * tig] =
                make_float2(__uint_as_float(f2tf(p2)), __uint_as_float(f2tf(p3)));
        }
        rs0 += __shfl_xor_sync(0xffffffffu, rs0, 1);
        rs0 += __shfl_xor_sync(0xffffffffu, rs0, 2);
        rs1 += __shfl_xor_sync(0xffffffffu, rs1, 1);
        rs1 += __shfl_xor_sync(0xffffffffu, rs1, 2);
        l0 = l0 * corr0 + rs0;
        l1 = l1 * corr1 + rs1;
        __syncwarp();

        // ---- O[16x64] += P . V ----
        #pragma unroll
        for (int k0 = 0; k0 < 8; k0++) {
            unsigned ap[4];
            ap[0] = __float_as_uint(Ps[qrow * 68 + k0 * 8 + tig]);
            ap[1] = __float_as_uint(Ps[(qrow + 8) * 68 + k0 * 8 + tig]);
            ap[2] = __float_as_uint(Ps[qrow * 68 + k0 * 8 + tig + 4]);
            ap[3] = __float_as_uint(Ps[(qrow + 8) * 68 + k0 * 8 + tig + 4]);
            #pragma unroll
            for (int n0 = 0; n0 < 8; n0++) {
                unsigned b0 = __float_as_uint(Vs[(k0 * 8 + tig) * 72 + n0 * 8 + gid]);
                unsigned b1 = __float_as_uint(Vs[(k0 * 8 + tig + 4) * 72 + n0 * 8 + gid]);
                mma8(o[n0], ap, b0, b1);
            }
        }
        __syncthreads();
    }

    // ---- epilogue: normalize, write g_O ----
    const float inv0 = 1.0f / l0, inv1 = 1.0f / l1;
    const int bb = bh >> 2, h = bh & 3;
    const int r0 = qt * 128 + qrow;
    size_t base0 = (size_t)(bb * SEQ + r0) * DM + h * 64;
    size_t base1 = base0 + (size_t)8 * DM;
    #pragma unroll
    for (int n0 = 0; n0 < 8; n0++) {
        *(float2*)&g_O[base0 + n0 * 8 + 2 * tig] =
            make_float2(o[n0][0] * inv0, o[n0][1] * inv0);
        *(float2*)&g_O[base1 + n0 * 8 + 2 * tig] =
            make_float2(o[n0][2] * inv1, o[n0][3] * inv1);
    }
}

// =====================================================================
// Kernel 3: output projection — bf16-split mma.  d_out = g_O @ Wo + bo
// =====================================================================
__global__ __launch_bounds__(256) void out_kernel(const float* __restrict__ Wo,
                                                  const float* __restrict__ bo,
                                                  float* __restrict__ out)
{
    __shared__ unsigned short Ah[64 * 18], Al[64 * 18];
    __shared__ unsigned short Bh[64 * 18], Bl[64 * 18];
    const int m0 = blockIdx.x * 64;
    const int n0 = blockIdx.y * 64;
    const int tid  = threadIdx.x;
    const int w    = tid >> 5;
    const int lane = tid & 31;
    const int gid  = lane >> 2, tig = lane & 3;
    const int mrow = (w & 3) * 16;
    const int nc0  = (w >> 2) * 32;

    float acc[4][4] = {};
    for (int k0 = 0; k0 < DM; k0 += 16) {
        {
            int i = tid >> 2, c = tid & 3;
            float4 a = *(const float4*)&g_O[(size_t)(m0 + i) * DM + k0 + c * 4];
            float av[4] = {a.x, a.y, a.z, a.w};
            #pragma unroll
            for (int u = 0; u < 4; u++)
                bsplit(av[u], Ah[i * 18 + c * 4 + u], Al[i * 18 + c * 4 + u]);
            int kk = tid >> 4, c2 = tid & 15;
            float4 wv = *(const float4*)&Wo[(size_t)(k0 + kk) * DM + n0 + c2 * 4];
            float wf[4] = {wv.x, wv.y, wv.z, wv.w};
            #pragma unroll
            for (int u = 0; u < 4; u++)
                bsplit(wf[u], Bh[(c2 * 4 + u) * 18 + kk], Bl[(c2 * 4 + u) * 18 + kk]);
        }
        __syncthreads();
        unsigned ah[4], al[4];
        ah[0] = *(const unsigned*)&Ah[(mrow + gid)     * 18 + 2 * tig];
        ah[1] = *(const unsigned*)&Ah[(mrow + gid + 8) * 18 + 2 * tig];
        ah[2] = *(const unsigned*)&Ah[(mrow + gid)     * 18 + 8 + 2 * tig];
        ah[3] = *(const unsigned*)&Ah[(mrow + gid + 8) * 18 + 8 + 2 * tig];
        al[0] = *(const unsigned*)&Al[(mrow + gid)     * 18 + 2 * tig];
        al[1] = *(const unsigned*)&Al[(mrow + gid + 8) * 18 + 2 * tig];
        al[2] = *(const unsigned*)&Al[(mrow + gid)     * 18 + 8 + 2 * tig];
        al[3] = *(const unsigned*)&Al[(mrow + gid + 8) * 18 + 8 + 2 * tig];
        #pragma unroll
        for (int nt = 0; nt < 4; nt++) {
            int n = nc0 + nt * 8 + gid;
            unsigned bh0 = *(const unsigned*)&Bh[n * 18 + 2 * tig];
            unsigned bh1 = *(const unsigned*)&Bh[n * 18 + 8 + 2 * tig];
            unsigned bl0 = *(const unsigned*)&Bl[n * 18 + 2 * tig];
            unsigned bl1 = *(const unsigned*)&Bl[n * 18 + 8 + 2 * tig];
            mmabf(acc[nt], ah, bh0, bh1);
            mmabf(acc[nt], al, bh0, bh1);
            mmabf(acc[nt], ah, bl0, bl1);
        }
        __syncthreads();
    }

    const int r0 = m0 + mrow + gid;
    #pragma unroll
    for (int nt = 0; nt < 4; nt++) {
        int c0 = n0 + nc0 + nt * 8 + 2 * tig;
        *(float2*)&out[(size_t)r0 * DM + c0] =
            make_float2(acc[nt][0] + bo[c0], acc[nt][1] + bo[c0 + 1]);
        *(float2*)&out[(size_t)(r0 + 8) * DM + c0] =
            make_float2(acc[nt][2] + bo[c0], acc[nt][3] + bo[c0 + 1]);
    }
}

// =====================================================================
extern "C" void kernel_launch(void* const* d_in, const int* in_sizes, int n_in,
                              void* d_out, int out_size)
{
    const float* query = (const float*)d_in[0];
    const float* key_  = (const float*)d_in[1];
    const float* value = (const float*)d_in[2];
    const float* Wq    = (const float*)d_in[3];
    const float* bq    = (const float*)d_in[4];
    const float* Wk    = (const float*)d_in[5];
    const float* bk    = (const float*)d_in[6];
    const float* Wv    = (const float*)d_in[7];
    const float* bv    = (const float*)d_in[8];
    const float* W2    = (const float*)d_in[9];
    const float* alpha = (const float*)d_in[10];
    const float* Wo    = (const float*)d_in[11];
    const float* bo    = (const float*)d_in[12];
    float* out = (float*)d_out;

    cudaFuncSetAttribute(prep_kernel, cudaFuncAttributeMaxDynamicSharedMemorySize, PREP_SMEM);
    cudaFuncSetAttribute(attn_kernel, cudaFuncAttributeMaxDynamicSharedMemorySize, ATTN_SMEM);

    prep_kernel<<<NH, 256, PREP_SMEM>>>(W2, alpha, Wk, bk);
    proj_kernel<<<dim3(128, 4, 3), 256>>>(query, key_, value, Wq, bq, Wv, bv);
    attn_kernel<<<dim3(16, BHT), 256, ATTN_SMEM>>>();
    out_kernel<<<dim3(128, 4), 256>>>(Wo, bo, out);
}

// round 17
// speedup vs baseline: 1.0077x; 1.0030x over previous
#include <cuda_runtime.h>
#include <cuda_bf16.h>
#include <math.h>

#define B_   4
#define SEQ  2048
#define DM   256
#define NH   4
#define DH   64
#define BHT  16       // B_*NH

// ---------------- scratch (device globals; no allocation) ----------------
__device__ float g_Q [BHT * SEQ * DH];   // [bh][s][64] tf32-rounded, k-permuted, x1/8
__device__ float g_K [BHT * SEQ * DH];   // effective K = K·G^T, tf32-rounded, k-permuted
__device__ float g_V [BHT * SEQ * DH];   // tf32-rounded, plain layout
__device__ float g_O [B_  * SEQ * DM];   // attn output
__device__ float g_Wk[DM * DM];          // folded Wk_eff
__device__ float g_bk[DM];               // folded bk_eff

// ---------------- helpers ----------------
__device__ __forceinline__ unsigned f2tf(float f) {
    unsigned u; asm("cvt.rna.tf32.f32 %0, %1;" : "=r"(u) : "f"(f)); return u;
}
__device__ __forceinline__ void mma8(float c[4], const unsigned a[4], unsigned b0, unsigned b1) {
    asm volatile(
        "mma.sync.aligned.m16n8k8.row.col.f32.tf32.tf32.f32 "
        "{%0,%1,%2,%3}, {%4,%5,%6,%7}, {%8,%9}, {%0,%1,%2,%3};\n"
        : "+f"(c[0]), "+f"(c[1]), "+f"(c[2]), "+f"(c[3])
        : "r"(a[0]), "r"(a[1]), "r"(a[2]), "r"(a[3]), "r"(b0), "r"(b1));
}
__device__ __forceinline__ void mmabf(float c[4], const unsigned a[4], unsigned b0, unsigned b1) {
    asm volatile(
        "mma.sync.aligned.m16n8k16.row.col.f32.bf16.bf16.f32 "
        "{%0,%1,%2,%3}, {%4,%5,%6,%7}, {%8,%9}, {%0,%1,%2,%3};\n"
        : "+f"(c[0]), "+f"(c[1]), "+f"(c[2]), "+f"(c[3])
        : "r"(a[0]), "r"(a[1]), "r"(a[2]), "r"(a[3]), "r"(b0), "r"(b1));
}
__device__ __forceinline__ void bsplit(float x, unsigned short& hi, unsigned short& lo) {
    __nv_bfloat16 h = __float2bfloat16_rn(x);
    float r = x - __bfloat162float(h);
    __nv_bfloat16 l = __float2bfloat16_rn(r);
    hi = *(unsigned short*)&h;
    lo = *(unsigned short*)&l;
}
// permute within 8-group so (k, k+4) land adjacent: j<4 -> 2j ; j>=4 -> 2j-7
__device__ __forceinline__ int p8(int j) { return (j < 4) ? 2 * j : 2 * j - 7; }

// =====================================================================
// Kernel 0: prep — fold TT interaction into Wk.
//   M_h[d,e] = sum_{a,r} W2[h,d,a,r] * W2[h,a,e,r];  G = I + (alpha/64) M
// =====================================================================
#define PREP_SMEM ((64 * 256 + 64 * 65) * 4)

__global__ __launch_bounds__(256) void prep_kernel(const float* __restrict__ W2,
                                                   const float* __restrict__ alpha_p,
                                                   const float* __restrict__ Wk,
                                                   const float* __restrict__ bk)
{
    extern __shared__ float sm[];
    float* Ws = sm;              // 64 x 256
    float* Gs = sm + 64 * 256;   // 64 x 65
    const int h = blockIdx.x;
    const int tid = threadIdx.x;
    const float* W2h = W2 + (size_t)h * 64 * 256;

    for (int idx = tid; idx < 64 * 256; idx += 256) Ws[idx] = W2h[idx];
    __syncthreads();

    const float c = alpha_p[0] * (1.0f / 64.0f);
    for (int idx = tid; idx < 64 * 64; idx += 256) {
        int d = idx >> 6, e = idx & 63;
        float s = 0.f;
        #pragma unroll 8
        for (int a = 0; a < 64; a++) {
            float4 wa = *(const float4*)&Ws[d * 256 + a * 4];
            float4 wb = *(const float4*)&Ws[a * 256 + e * 4];
            s += wa.x * wb.x + wa.y * wb.y + wa.z * wb.z + wa.w * wb.w;
        }
        Gs[d * 65 + e] = c * s + ((d == e) ? 1.0f : 0.0f);
    }
    __syncthreads();

    {
        const int cr = tid;
        float kin[64];
        #pragma unroll
        for (int e = 0; e < 64; e++) kin[e] = Wk[(size_t)cr * DM + h * 64 + e];
        for (int d = 0; d < 64; d++) {
            float s = 0.f;
            #pragma unroll
            for (int e = 0; e < 64; e++) s += kin[e] * Gs[d * 65 + e];
            g_Wk[(size_t)cr * DM + h * 64 + d] = s;
        }
    }
    if (tid < 64) {
        int d = tid;
        float s = 0.f;
        #pragma unroll
        for (int e = 0; e < 64; e++) s += bk[h * 64 + e] * Gs[d * 65 + e];
        g_bk[h * 64 + d] = s;
    }
}

// =====================================================================
// Kernel 1: QKV projection — bf16-split mma (Ah·Bh + Al·Bh + Ah·Bl).
// 64x64 tile, 8 warps: warp w -> m-strip (w&3)*16, n-half (w>>2)*32 (4 n-tiles).
// Epilogue: Q/K -> tf32-rounded, k-permuted scatter; V -> tf32-rounded plain.
// =====================================================================
__global__ __launch_bounds__(256) void proj_kernel(
    const float* __restrict__ Xq, const float* __restrict__ Xk, const float* __restrict__ Xv,
    const float* __restrict__ Wq, const float* __restrict__ bq,
    const float* __restrict__ Wv, const float* __restrict__ bv)
{
    __shared__ unsigned short Ah[64 * 18], Al[64 * 18];
    __shared__ unsigned short Bh[64 * 18], Bl[64 * 18];
    const int z = blockIdx.z;
    const float* X    = (z == 0) ? Xq : (z == 1) ? Xk : Xv;
    const float* W    = (z == 0) ? Wq : (z == 1) ? g_Wk : Wv;
    const float* bias = (z == 0) ? bq : (z == 1) ? g_bk : bv;
    const int m0 = blockIdx.x * 64;
    const int n0 = blockIdx.y * 64;
    const int tid  = threadIdx.x;
    const int w    = tid >> 5;
    const int lane = tid & 31;
    const int gid  = lane >> 2, tig = lane & 3;
    const int mrow = (w & 3) * 16;
    const int nc0  = (w >> 2) * 32;

    float acc[4][4] = {};
    for (int k0 = 0; k0 < DM; k0 += 16) {
        {
            int i = tid >> 2, c = tid & 3;
            float4 a = *(const float4*)&X[(size_t)(m0 + i) * DM + k0 + c * 4];
            float av[4] = {a.x, a.y, a.z, a.w};
            #pragma unroll
            for (int u = 0; u < 4; u++)
                bsplit(av[u], Ah[i * 18 + c * 4 + u], Al[i * 18 + c * 4 + u]);
            int kk = tid >> 4, c2 = tid & 15;
            float4 wv = *(const float4*)&W[(size_t)(k0 + kk) * DM + n0 + c2 * 4];
            float wf[4] = {wv.x, wv.y, wv.z, wv.w};
            #pragma unroll
            for (int u = 0; u < 4; u++)
                bsplit(wf[u], Bh[(c2 * 4 + u) * 18 + kk], Bl[(c2 * 4 + u) * 18 + kk]);
        }
        __syncthreads();
        unsigned ah[4], al[4];
        ah[0] = *(const unsigned*)&Ah[(mrow + gid)     * 18 + 2 * tig];
        ah[1] = *(const unsigned*)&Ah[(mrow + gid + 8) * 18 + 2 * tig];
        ah[2] = *(const unsigned*)&Ah[(mrow + gid)     * 18 + 8 + 2 * tig];
        ah[3] = *(const unsigned*)&Ah[(mrow + gid + 8) * 18 + 8 + 2 * tig];
        al[0] = *(const unsigned*)&Al[(mrow + gid)     * 18 + 2 * tig];
        al[1] = *(const unsigned*)&Al[(mrow + gid + 8) * 18 + 2 * tig];
        al[2] = *(const unsigned*)&Al[(mrow + gid)     * 18 + 8 + 2 * tig];
        al[3] = *(const unsigned*)&Al[(mrow + gid + 8) * 18 + 8 + 2 * tig];
        #pragma unroll
        for (int nt = 0; nt < 4; nt++) {
            int n = nc0 + nt * 8 + gid;
            unsigned bh0 = *(const unsigned*)&Bh[n * 18 + 2 * tig];
            unsigned bh1 = *(const unsigned*)&Bh[n * 18 + 8 + 2 * tig];
            unsigned bl0 = *(const unsigned*)&Bl[n * 18 + 2 * tig];
            unsigned bl1 = *(const unsigned*)&Bl[n * 18 + 8 + 2 * tig];
            mmabf(acc[nt], ah, bh0, bh1);
            mmabf(acc[nt], al, bh0, bh1);
            mmabf(acc[nt], ah, bl0, bl1);
        }
        __syncthreads();
    }

    const int h = n0 >> 6;
    float* dst = (z == 0) ? g_Q : (z == 1) ? g_K : g_V;
    const float sc = (z == 0) ? 0.125f : 1.0f;
    const int r0 = m0 + mrow + gid;
    #pragma unroll
    for (int nt = 0; nt < 4; nt++) {
        int ch0 = nc0 + nt * 8 + 2 * tig;     // head-local col
        int ch1 = ch0 + 1;
        float v[2][2];
        v[0][0] = (acc[nt][0] + bias[n0 + ch0]) * sc;
        v[0][1] = (acc[nt][1] + bias[n0 + ch1]) * sc;
        v[1][0] = (acc[nt][2] + bias[n0 + ch0]) * sc;
        v[1][1] = (acc[nt][3] + bias[n0 + ch1]) * sc;
        #pragma unroll
        for (int rr = 0; rr < 2; rr++) {
            int m = r0 + rr * 8;
            int b = m >> 11, s = m & (SEQ - 1);
            size_t base = (size_t)((b * NH + h) * SEQ + s) * DH;
            float t0 = __uint_as_float(f2tf(v[rr][0]));
            float t1 = __uint_as_float(f2tf(v[rr][1]));
            if (z < 2) {   // permuted k layout for Q/K
                dst[base + (ch0 & ~7) + p8(ch0 & 7)] = t0;
                dst[base + (ch1 & ~7) + p8(ch1 & 7)] = t1;
            } else {
                dst[base + ch0] = t0;
                dst[base + ch1] = t1;
            }
        }
    }
}

// =====================================================================
// Kernel 2: flash attention via mma.sync m16n8k8 tf32.
// g_Q/g_K pre-rounded + k-permuted -> S-phase fragments are LDS.64.
// Qs/Ks stride 72 (8B pair-bank = 4*gid+tig, conflict-free); Vs 72; Ps 68.
// =====================================================================
#define ATTN_SMEM ((128 * 72 + 64 * 72 + 64 * 72) * 4)   // 73,728 B

__global__ __launch_bounds__(256, 2) void attn_kernel()
{
    extern __shared__ float sm[];
    float* Qs = sm;                   // 128x72; becomes Ps after prologue
    float* Ps = sm;                   // 128x68 view (tf32 bits of P)
    float* Ks = sm + 128 * 72;        // 64x72
    float* Vs = Ks + 64 * 72;         // 64x72
    const int bh = blockIdx.y;
    const int qt = blockIdx.x;
    const int tid  = threadIdx.x;
    const int w    = tid >> 5;
    const int lane = tid & 31;
    const int gid  = lane >> 2;       // 0..7
    const int tig  = lane & 3;        // 0..3

    // ---- prologue: copy Q tile (pre-rounded, permuted) ----
    const float* Qg = g_Q + (size_t)(bh * SEQ + qt * 128) * DH;
    #pragma unroll
    for (int it = 0; it < 8; it++) {
        int idx = tid + it * 256;
        int i = idx >> 4, c = idx & 15;
        *(float4*)&Qs[i * 72 + c * 4] = *(const float4*)&Qg[i * DH + c * 4];
    }
    __syncthreads();

    // ---- Q fragments to registers (LDS.64 pairs) ----
    const int qrow = w * 16 + gid;
    unsigned aq[8][4];
    #pragma unroll
    for (int k0 = 0; k0 < 8; k0++) {
        uint2 qa = *(const uint2*)&Qs[qrow * 72 + k0 * 8 + 2 * tig];
        uint2 qb = *(const uint2*)&Qs[(qrow + 8) * 72 + k0 * 8 + 2 * tig];
        aq[k0][0] = qa.x; aq[k0][1] = qb.x; aq[k0][2] = qa.y; aq[k0][3] = qb.y;
    }

    float m0 = -1e30f, m1 = -1e30f, l0 = 0.f, l1 = 0.f;
    float o[8][4] = {};

    for (int kt = 0; kt < 32; kt++) {
        const float* Kg = g_K + (size_t)(bh * SEQ + kt * 64) * DH;
        const float* Vg = g_V + (size_t)(bh * SEQ + kt * 64) * DH;
        #pragma unroll
        for (int it = 0; it < 4; it++) {
            int idx = tid + it * 256;
            int i = idx >> 4, c = idx & 15;
            *(float4*)&Ks[i * 72 + c * 4] = *(const float4*)&Kg[i * DH + c * 4];
            *(float4*)&Vs[i * 72 + c * 4] = *(const float4*)&Vg[i * DH + c * 4];
        }
        __syncthreads();

        // ---- S[16x64] = Q . K^T  (b fragment = one LDS.64) ----
        float s[8][4] = {};
        #pragma unroll
        for (int k0 = 0; k0 < 8; k0++) {
            #pragma unroll
            for (int n0 = 0; n0 < 8; n0++) {
                uint2 bb = *(const uint2*)&Ks[(n0 * 8 + gid) * 72 + k0 * 8 + 2 * tig];
                mma8(s[n0], aq[k0], bb.x, bb.y);
            }
        }

        // ---- online softmax (rows qrow and qrow+8) ----
        float rx0 = -1e30f, rx1 = -1e30f;
        #pragma unroll
        for (int n0 = 0; n0 < 8; n0++) {
            rx0 = fmaxf(rx0, fmaxf(s[n0][0], s[n0][1]));
            rx1 = fmaxf(rx1, fmaxf(s[n0][2], s[n0][3]));
        }
        rx0 = fmaxf(rx0, __shfl_xor_sync(0xffffffffu, rx0, 1));
        rx0 = fmaxf(rx0, __shfl_xor_sync(0xffffffffu, rx0, 2));
        rx1 = fmaxf(rx1, __shfl_xor_sync(0xffffffffu, rx1, 1));
        rx1 = fmaxf(rx1, __shfl_xor_sync(0xffffffffu, rx1, 2));
        float mn0 = fmaxf(m0, rx0), mn1 = fmaxf(m1, rx1);
        float corr0 = __expf(m0 - mn0), corr1 = __expf(m1 - mn1);
        m0 = mn0; m1 = mn1;
        float rs0 = 0.f, rs1 = 0.f;
        #pragma unroll
        for (int n0 = 0; n0 < 8; n0++) {
            float p0 = __expf(s[n0][0] - mn0);
            float p1 = __expf(s[n0][1] - mn0);
            float p2 = __expf(s[n0][2] - mn1);
            float p3 = __expf(s[n0][3] - mn1);
            rs0 += p0 + p1; rs1 += p2 + p3;
            o[n0][0] *= corr0; o[n0][1] *= corr0;
            o[n0][2] *= corr1; o[n0][3] *= corr1;
            *(float2*)&Ps[qrow * 68 + n0 * 8 + 2 * tig] =
                make_float2(__uint_as_float(f2tf(p0)), __uint_as_float(f2tf(p1)));
            *(float2*)&Ps[(qrow + 8) * 68 + n0 * 8 + 2 * tig] =
                make_float2(__uint_as_float(f2tf(p2)), __uint_as_float(f2tf(p3)));
        }
        rs0 += __shfl_xor_sync(0xffffffffu, rs0, 1);
        rs0 += __shfl_xor_sync(0xffffffffu, rs0, 2);
        rs1 += __shfl_xor_sync(0xffffffffu, rs1, 1);
        rs1 += __shfl_xor_sync(0xffffffffu, rs1, 2);
        l0 = l0 * corr0 + rs0;
        l1 = l1 * corr1 + rs1;
        __syncwarp();

        // ---- O[16x64] += P . V ----
        #pragma unroll
        for (int k0 = 0; k0 < 8; k0++) {
            unsigned ap[4];
            ap[0] = __float_as_uint(Ps[qrow * 68 + k0 * 8 + tig]);
            ap[1] = __float_as_uint(Ps[(qrow + 8) * 68 + k0 * 8 + tig]);
            ap[2] = __float_as_uint(Ps[qrow * 68 + k0 * 8 + tig + 4]);
            ap[3] = __float_as_uint(Ps[(qrow + 8) * 68 + k0 * 8 + tig + 4]);
            #pragma unroll
            for (int n0 = 0; n0 < 8; n0++) {
                unsigned b0 = __float_as_uint(Vs[(k0 * 8 + tig) * 72 + n0 * 8 + gid]);
                unsigned b1 = __float_as_uint(Vs[(k0 * 8 + tig + 4) * 72 + n0 * 8 + gid]);
                mma8(o[n0], ap, b0, b1);
            }
        }
        __syncthreads();
    }

    // ---- epilogue: normalize, write g_O ----
    const float inv0 = 1.0f / l0, inv1 = 1.0f / l1;
    const int bb = bh >> 2, h = bh & 3;
    const int r0 = qt * 128 + qrow;
    size_t base0 = (size_t)(bb * SEQ + r0) * DM + h * 64;
    size_t base1 = base0 + (size_t)8 * DM;
    #pragma unroll
    for (int n0 = 0; n0 < 8; n0++) {
        *(float2*)&g_O[base0 + n0 * 8 + 2 * tig] =
            make_float2(o[n0][0] * inv0, o[n0][1] * inv0);
        *(float2*)&g_O[base1 + n0 * 8 + 2 * tig] =
            make_float2(o[n0][2] * inv1, o[n0][3] * inv1);
    }
}

// =====================================================================
// Kernel 3: output projection — bf16-split mma.  d_out = g_O @ Wo + bo
// =====================================================================
__global__ __launch_bounds__(256) void out_kernel(const float* __restrict__ Wo,
                                                  const float* __restrict__ bo,
                                                  float* __restrict__ out)
{
    __shared__ unsigned short Ah[64 * 18], Al[64 * 18];
    __shared__ unsigned short Bh[64 * 18], Bl[64 * 18];
    const int m0 = blockIdx.x * 64;
    const int n0 = blockIdx.y * 64;
    const int tid  = threadIdx.x;
    const int w    = tid >> 5;
    const int lane = tid & 31;
    const int gid  = lane >> 2, tig = lane & 3;
    const int mrow = (w & 3) * 16;
    const int nc0  = (w >> 2) * 32;

    float acc[4][4] = {};
    for (int k0 = 0; k0 < DM; k0 += 16) {
        {
            int i = tid >> 2, c = tid & 3;
            float4 a = *(const float4*)&g_O[(size_t)(m0 + i) * DM + k0 + c * 4];
            float av[4] = {a.x, a.y, a.z, a.w};
            #pragma unroll
            for (int u = 0; u < 4; u++)
                bsplit(av[u], Ah[i * 18 + c * 4 + u], Al[i * 18 + c * 4 + u]);
            int kk = tid >> 4, c2 = tid & 15;
            float4 wv = *(const float4*)&Wo[(size_t)(k0 + kk) * DM + n0 + c2 * 4];
            float wf[4] = {wv.x, wv.y, wv.z, wv.w};
            #pragma unroll
            for (int u = 0; u < 4; u++)
                bsplit(wf[u], Bh[(c2 * 4 + u) * 18 + kk], Bl[(c2 * 4 + u) * 18 + kk]);
        }
        __syncthreads();
        unsigned ah[4], al[4];
        ah[0] = *(const unsigned*)&Ah[(mrow + gid)     * 18 + 2 * tig];
        ah[1] = *(const unsigned*)&Ah[(mrow + gid + 8) * 18 + 2 * tig];
        ah[2] = *(const unsigned*)&Ah[(mrow + gid)     * 18 + 8 + 2 * tig];
        ah[3] = *(const unsigned*)&Ah[(mrow + gid + 8) * 18 + 8 + 2 * tig];
        al[0] = *(const unsigned*)&Al[(mrow + gid)     * 18 + 2 * tig];
        al[1] = *(const unsigned*)&Al[(mrow + gid + 8) * 18 + 2 * tig];
        al[2] = *(const unsigned*)&Al[(mrow + gid)     * 18 + 8 + 2 * tig];
        al[3] = *(const unsigned*)&Al[(mrow + gid + 8) * 18 + 8 + 2 * tig];
        #pragma unroll
        for (int nt = 0; nt < 4; nt++) {
            int n = nc0 + nt * 8 + gid;
            unsigned bh0 = *(const unsigned*)&Bh[n * 18 + 2 * tig];
            unsigned bh1 = *(const unsigned*)&Bh[n * 18 + 8 + 2 * tig];
            unsigned bl0 = *(const unsigned*)&Bl[n * 18 + 2 * tig];
            unsigned bl1 = *(const unsigned*)&Bl[n * 18 + 8 + 2 * tig];
            mmabf(acc[nt], ah, bh0, bh1);
            mmabf(acc[nt], al, bh0, bh1);
            mmabf(acc[nt], ah, bl0, bl1);
        }
        __syncthreads();
    }

    const int r0 = m0 + mrow + gid;
    #pragma unroll
    for (int nt = 0; nt < 4; nt++) {
        int c0 = n0 + nc0 + nt * 8 + 2 * tig;
        *(float2*)&out[(size_t)r0 * DM + c0] =
            make_float2(acc[nt][0] + bo[c0], acc[nt][1] + bo[c0 + 1]);
        *(float2*)&out[(size_t)(r0 + 8) * DM + c0] =
            make_float2(acc[nt][2] + bo[c0], acc[nt][3] + bo[c0 + 1]);
    }
}

// =====================================================================
extern "C" void kernel_launch(void* const* d_in, const int* in_sizes, int n_in,
                              void* d_out, int out_size)
{
    const float* query = (const float*)d_in[0];
    const float* key_  = (const float*)d_in[1];
    const float* value = (const float*)d_in[2];
    const float* Wq    = (const float*)d_in[3];
    const float* bq    = (const float*)d_in[4];
    const float* Wk    = (const float*)d_in[5];
    const float* bk    = (const float*)d_in[6];
    const float* Wv    = (const float*)d_in[7];
    const float* bv    = (const float*)d_in[8];
    const float* W2    = (const float*)d_in[9];
    const float* alpha = (const float*)d_in[10];
    const float* Wo    = (const float*)d_in[11];
    const float* bo    = (const float*)d_in[12];
    float* out = (float*)d_out;

    cudaFuncSetAttribute(prep_kernel, cudaFuncAttributeMaxDynamicSharedMemorySize, PREP_SMEM);
    cudaFuncSetAttribute(attn_kernel, cudaFuncAttributeMaxDynamicSharedMemorySize, ATTN_SMEM);

    prep_kernel<<<NH, 256, PREP_SMEM>>>(W2, alpha, Wk, bk);
    proj_kernel<<<dim3(128, 4, 3), 256>>>(query, key_, value, Wq, bq, Wv, bv);
    attn_kernel<<<dim3(16, BHT), 256, ATTN_SMEM>>>();
    out_kernel<<<dim3(128, 4), 256>>>(Wo, bo, out);
}